// round 13
// baseline (speedup 1.0000x reference)
#include <cuda_runtime.h>
#include <cuda_fp16.h>
#include <stdint.h>

#define Q_N   4096
#define D_N   32768
#define DIM   128
#define TQ    128
#define TN    128
#define LDSK  136                    // padded smem row stride in f16 elems (272 B)
#define ROWB  272
#define NSLICE 64
#define SUBS  ((D_N / TN) / NSLICE)  // 4 D-subtiles per CTA
#define TILE_E (TQ * LDSK)
#define NBLK16 (D_N / 16)            // 2048 16-col blocks per row
#define MARGIN 1.25f
#define CAND_CAP 256

// ---- device scratch ----
__device__ __half g_qh[Q_N * DIM];
__device__ __half g_dh[D_N * DIM];
__device__ unsigned short g_lmax16[(size_t)Q_N * NBLK16];   // 16 MB, f16 bits
__device__ float g_ms[Q_N];
__device__ float g_comb[Q_N];
__device__ int   g_done;

// ---- helpers ----
__device__ __forceinline__ uint32_t smem_u32(const void* p) {
    uint32_t a;
    asm("{ .reg .u64 t; cvta.to.shared.u64 t, %1; cvt.u32.u64 %0, t; }" : "=r"(a) : "l"(p));
    return a;
}
__device__ __forceinline__ void cpa16(void* s, const void* g) {
    unsigned sa = smem_u32(s);
    asm volatile("cp.async.cg.shared.global [%0], [%1], 16;" :: "r"(sa), "l"(g));
}
#define CP_COMMIT() asm volatile("cp.async.commit_group;" ::: "memory")
#define CP_WAIT0()  asm volatile("cp.async.wait_group 0;" ::: "memory")

__device__ __forceinline__ void load_tile(__half* dst, const __half* gsrc, int tid) {
#pragma unroll
    for (int t = 0; t < 8; t++) {
        int chunk = tid + t * 256;
        int row = chunk >> 4;
        int c   = chunk & 15;
        cpa16(dst + row * LDSK + c * 8, gsrc + row * DIM + c * 8);
    }
}
__device__ __forceinline__ void ldm_x4(uint32_t* r, uint32_t addr) {
    asm volatile("ldmatrix.sync.aligned.m8n8.x4.shared.b16 {%0,%1,%2,%3}, [%4];"
        : "=r"(r[0]), "=r"(r[1]), "=r"(r[2]), "=r"(r[3]) : "r"(addr));
}
// f16 x f16 -> f16 accum mma
__device__ __forceinline__ void mma_f16(uint32_t* c, const uint32_t* a, uint32_t b0, uint32_t b1) {
    asm volatile(
        "mma.sync.aligned.m16n8k16.row.col.f16.f16.f16.f16 "
        "{%0,%1}, {%2,%3,%4,%5}, {%6,%7}, {%0,%1};\n"
        : "+r"(c[0]), "+r"(c[1])
        : "r"(a[0]), "r"(a[1]), "r"(a[2]), "r"(a[3]), "r"(b0), "r"(b1));
}
__device__ __forceinline__ float bits_f16(unsigned short u) {
    __half h = *reinterpret_cast<__half*>(&u);
    return __half2float(h);
}
__device__ __forceinline__ uint32_t pack_h2(float a, float b) {
    __half2 h = __floats2half2_rn(a, b);
    return *reinterpret_cast<uint32_t*>(&h);
}

// =====================================================================
// Pass 0: fp32 -> fp16, 32B-read / 16B-write per step; reset counter
// =====================================================================
__global__ void convert_kernel(const float4* __restrict__ qe, const float4* __restrict__ de) {
    const int i = blockIdx.x * blockDim.x + threadIdx.x;   // 0 .. D_N*DIM/8-1
    {
        float4 v0 = de[2 * i], v1 = de[2 * i + 1];
        uint4 o;
        o.x = pack_h2(v0.x, v0.y); o.y = pack_h2(v0.z, v0.w);
        o.z = pack_h2(v1.x, v1.y); o.w = pack_h2(v1.z, v1.w);
        ((uint4*)g_dh)[i] = o;
    }
    if (i < Q_N * DIM / 8) {
        float4 v0 = qe[2 * i], v1 = qe[2 * i + 1];
        uint4 o;
        o.x = pack_h2(v0.x, v0.y); o.y = pack_h2(v0.z, v0.w);
        o.z = pack_h2(v1.x, v1.y); o.w = pack_h2(v1.z, v1.w);
        ((uint4*)g_qh)[i] = o;
    }
    if (i == 0) g_done = 0;
}

// =====================================================================
// Pass 1: f16 GEMM (f16 accum), A register-resident, B-only smem traffic,
//         per-(row, 16-col block) f16 max table  [core identical to R8]
// =====================================================================
__global__ __launch_bounds__(256, 2) void approx_kernel() {
    extern __shared__ __half sm[];
    __half* As    = sm;                 // [128 x LDSK]
    __half* Bbase = As + TILE_E;        // 2 x [128 x LDSK]

    const int tid  = threadIdx.x;
    const int wid  = tid >> 5;
    const int lane = tid & 31;
    const int g    = lane >> 2;
    const int qr   = lane & 3;
    const int wid_m = wid >> 1;
    const int wid_n = wid & 1;
    const int qtile = blockIdx.x;
    const int d0    = blockIdx.y * (SUBS * TN);

    load_tile(As, g_qh + (size_t)qtile * TQ * DIM, tid);
    load_tile(Bbase, g_dh + (size_t)d0 * DIM, tid);
    CP_COMMIT();

    const int rowA  = wid_m * 32 + (lane & 15);
    const int colAb = ((lane >> 4) & 1) * 16;
    const uint32_t aBase = smem_u32(As) + rowA * ROWB + colAb;
    const int rowB  = wid_n * 64 + (lane & 7) + ((lane >> 4) << 3);
    const int colBb = ((lane >> 3) & 1) * 16;
    const uint32_t b_lane_off = (uint32_t)(rowB * ROWB + colBb);
    const uint32_t b_smem0 = smem_u32(Bbase);

    const int row0 = qtile * TQ + wid_m * 32 + g;

    CP_WAIT0();
    __syncthreads();

    uint32_t aF[2][8][4];
#pragma unroll
    for (int ks = 0; ks < 8; ks++) {
        ldm_x4(aF[0][ks], aBase + (uint32_t)(ks * 32));
        ldm_x4(aF[1][ks], aBase + 16 * ROWB + (uint32_t)(ks * 32));
    }

    for (int s = 0; s < SUBS; s++) {
        if (s > 0) { CP_WAIT0(); __syncthreads(); }
        if (s + 1 < SUBS) {
            load_tile(Bbase + ((s + 1) & 1) * TILE_E, g_dh + (size_t)(d0 + (s + 1) * TN) * DIM, tid);
            CP_COMMIT();
        }
        const uint32_t bH_base = b_smem0 + (uint32_t)(s & 1) * (TILE_E * 2) + b_lane_off;

        uint32_t acc[2][8][2];
#pragma unroll
        for (int mt = 0; mt < 2; mt++)
#pragma unroll
            for (int nt = 0; nt < 8; nt++) { acc[mt][nt][0] = 0u; acc[mt][nt][1] = 0u; }

#pragma unroll
        for (int ks = 0; ks < 8; ks++) {
            const uint32_t ko = (uint32_t)(ks * 32);
            uint32_t bH[4][4];
#pragma unroll
            for (int p = 0; p < 4; p++)
                ldm_x4(bH[p], bH_base + (uint32_t)(p * 16 * ROWB) + ko);
#pragma unroll
            for (int mt = 0; mt < 2; mt++)
#pragma unroll
                for (int p = 0; p < 4; p++) {
                    mma_f16(acc[mt][2 * p],     aF[mt][ks], bH[p][0], bH[p][1]);
                    mma_f16(acc[mt][2 * p + 1], aF[mt][ks], bH[p][2], bH[p][3]);
                }
        }

        const int gblk = (blockIdx.y * SUBS + s) * 8 + wid_n * 4;
#pragma unroll
        for (int sl = 0; sl < 4; sl++) {
            const int mt = sl >> 1, rg = sl & 1;
            unsigned short outv[4];
#pragma unroll
            for (int b = 0; b < 4; b++) {
                __half2 h0 = *reinterpret_cast<const __half2*>(&acc[mt][2 * b][rg]);
                __half2 h1 = *reinterpret_cast<const __half2*>(&acc[mt][2 * b + 1][rg]);
                __half2 hm = __hmax2(h0, h1);
                float m = fmaxf(__half2float(__low2half(hm)), __half2float(__high2half(hm)));
#pragma unroll
                for (int off = 1; off < 4; off <<= 1)
                    m = fmaxf(m, __shfl_xor_sync(0xffffffffu, m, off));
                __half hv = __float2half_rn(m);
                outv[b] = *reinterpret_cast<unsigned short*>(&hv);
            }
            if (qr == 0) {
                ushort4 v; v.x = outv[0]; v.y = outv[1]; v.z = outv[2]; v.w = outv[3];
                *(ushort4*)(g_lmax16 + (size_t)(row0 + sl * 8) * NBLK16 + gblk) = v;
            }
        }
    }
}

// =====================================================================
// Pass 2: FUSED scan + exact + weight gather + (last block) final reduce
// =====================================================================
__global__ void __launch_bounds__(256) scanexact_kernel(const float* __restrict__ qe,
                                                        const float* __restrict__ de,
                                                        const int* __restrict__ qids,
                                                        const int* __restrict__ dids,
                                                        const float* __restrict__ qwt,
                                                        const float* __restrict__ dwt,
                                                        float* __restrict__ out) {
    const int row = blockIdx.x;
    const int t   = threadIdx.x;
    const int wid  = t >> 5;
    const int lane = t & 31;
    const bool hi  = (lane >= 16);
    __shared__ float red[256];
    __shared__ float sC[256];
    __shared__ int lcnt;
    __shared__ int sdone;
    __shared__ uint32_t lblk[CAND_CAP];
    __shared__ float    cval[CAND_CAP];
    __shared__ unsigned ccol[CAND_CAP];

    // --- scan phase ---
    uint4 raw = ((const uint4*)(g_lmax16 + (size_t)row * NBLK16))[t];
    float v[8];
    v[0] = bits_f16((unsigned short)(raw.x & 0xFFFF));
    v[1] = bits_f16((unsigned short)(raw.x >> 16));
    v[2] = bits_f16((unsigned short)(raw.y & 0xFFFF));
    v[3] = bits_f16((unsigned short)(raw.y >> 16));
    v[4] = bits_f16((unsigned short)(raw.z & 0xFFFF));
    v[5] = bits_f16((unsigned short)(raw.z >> 16));
    v[6] = bits_f16((unsigned short)(raw.w & 0xFFFF));
    v[7] = bits_f16((unsigned short)(raw.w >> 16));

    float m = v[0];
#pragma unroll
    for (int j = 1; j < 8; j++) m = fmaxf(m, v[j]);
    red[t] = m;
    if (t == 0) lcnt = 0;
    __syncthreads();
    for (int off = 128; off > 0; off >>= 1) {
        if (t < off) red[t] = fmaxf(red[t], red[t + off]);
        __syncthreads();
    }
    const float thr = red[0] - MARGIN;

#pragma unroll
    for (int j = 0; j < 8; j++) {
        if (v[j] >= thr) {
            int p = atomicAdd(&lcnt, 1);
            if (p < CAND_CAP) lblk[p] = (uint32_t)(t * 8 + j);
        }
    }
    __syncthreads();
    const int cnt = lcnt < CAND_CAP ? lcnt : CAND_CAP;

    // --- exact phase: warp e-strided over candidates ---
    const float4 q4 = ((const float4*)(qe + (size_t)row * DIM))[lane];

    for (int e = wid; e < cnt; e += 8) {
        const int col0 = (int)lblk[e] * 16;

        float p[16];
#pragma unroll
        for (int b = 0; b < 2; b++) {
            float4 d[8];
#pragma unroll
            for (int r = 0; r < 8; r++)
                d[r] = ((const float4*)(de + (size_t)(col0 + b * 8 + r) * DIM))[lane];
#pragma unroll
            for (int r = 0; r < 8; r++)
                p[b * 8 + r] = fmaf(q4.x, d[r].x, fmaf(q4.y, d[r].y, fmaf(q4.z, d[r].z, q4.w * d[r].w)));
        }

        float y[8];
#pragma unroll
        for (int j = 0; j < 8; j++) {
            float a = hi ? p[j + 8] : p[j];
            float b = hi ? p[j] : p[j + 8];
            y[j] = a + __shfl_xor_sync(0xffffffffu, b, 16);
        }
#pragma unroll
        for (int off = 1; off < 16; off <<= 1)
#pragma unroll
            for (int j = 0; j < 8; j++)
                y[j] += __shfl_xor_sync(0xffffffffu, y[j], off);

        float    s = y[0];
        unsigned c = (unsigned)(col0 + (hi ? 8 : 0));
#pragma unroll
        for (int j = 1; j < 8; j++)
            if (y[j] > s) { s = y[j]; c = (unsigned)(col0 + (hi ? 8 : 0) + j); }
        {
            float    os = __shfl_xor_sync(0xffffffffu, s, 16);
            unsigned oc = __shfl_xor_sync(0xffffffffu, c, 16);
            if (os > s || (os == s && oc < c)) { s = os; c = oc; }
        }
        if (lane == 0) { cval[e] = s; ccol[e] = c; }
    }
    __syncthreads();

    // --- final per-row reduce (warp 0); ties -> smaller column ---
    if (t < 32) {
        float    s = -3.402823466e38f;
        unsigned c = 0xFFFFFFFFu;
        for (int e = lane; e < cnt; e += 32) {
            float    es = cval[e];
            unsigned ec = ccol[e];
            if (es > s || (es == s && ec < c)) { s = es; c = ec; }
        }
#pragma unroll
        for (int off = 1; off < 32; off <<= 1) {
            float    os = __shfl_xor_sync(0xffffffffu, s, off);
            unsigned oc = __shfl_xor_sync(0xffffffffu, c, off);
            if (os > s || (os == s && oc < c)) { s = os; c = oc; }
        }
        if (lane == 0) {
            g_ms[row]   = s;
            g_comb[row] = qwt[qids[row]] * dwt[dids[(int)c]];
        }
    }

    // --- last block to finish performs the global reduction (fixed order
    //     -> deterministic result regardless of which block runs it) ---
    if (t == 0) {
        __threadfence();
        int prev = atomicAdd(&g_done, 1);
        sdone = (prev == Q_N - 1) ? 1 : 0;
    }
    __syncthreads();
    if (sdone) {
        __threadfence();                        // acquire all rows' g_ms/g_comb
        float a = 0.f, b = 0.f, c = 0.f;
#pragma unroll
        for (int j = 0; j < Q_N / 1024; j++) {  // 4 float4 strides
            float4 cm = ((const float4*)g_comb)[t + j * 256];
            float4 ms = ((const float4*)g_ms)[t + j * 256];
            a += (cm.x + cm.y) + (cm.z + cm.w);
            b += fmaf(cm.x, ms.x, fmaf(cm.y, ms.y, fmaf(cm.z, ms.z, cm.w * ms.w)));
            c += (ms.x + ms.y) + (ms.z + ms.w);
        }
        red[t] = a; cval[t] = b; sC[t] = c;     // reuse smem (cval is 256 floats)
        __syncthreads();
        for (int off = 128; off > 0; off >>= 1) {
            if (t < off) { red[t] += red[t + off]; cval[t] += cval[t + off]; sC[t] += sC[t + off]; }
            __syncthreads();
        }
        if (t == 0) out[0] = (red[0] > 0.f) ? (cval[0] / red[0]) : (sC[0] / (float)Q_N);
    }
}

// =====================================================================
// launch
// =====================================================================
extern "C" void kernel_launch(void* const* d_in, const int* in_sizes, int n_in,
                              void* d_out, int out_size) {
    const float* qe  = (const float*)d_in[0];
    const float* de  = (const float*)d_in[1];
    const int*   qid = (const int*)d_in[2];
    const int*   did = (const int*)d_in[3];
    const float* qwt = (const float*)d_in[4];
    const float* dwt = (const float*)d_in[5];
    float* out = (float*)d_out;

    size_t smem = (size_t)(3 * TILE_E) * sizeof(__half);   // 104,448 B -> 2 CTAs/SM
    cudaFuncSetAttribute(approx_kernel, cudaFuncAttributeMaxDynamicSharedMemorySize, (int)smem);

    convert_kernel<<<D_N * DIM / 8 / 256, 256>>>((const float4*)qe, (const float4*)de);
    approx_kernel<<<dim3(Q_N / TQ, NSLICE), 256, smem>>>();
    scanexact_kernel<<<Q_N, 256>>>(qe, de, qid, did, qwt, dwt, out);
}

// round 14
// speedup vs baseline: 1.0080x; 1.0080x over previous
#include <cuda_runtime.h>
#include <cuda_fp16.h>
#include <stdint.h>

#define Q_N   4096
#define D_N   32768
#define DIM   128
#define TQ    128
#define TN    128
#define LDSK  136                    // padded smem row stride in f16 elems (272 B)
#define ROWB  272
#define NSLICE 32
#define SUBS  ((D_N / TN) / NSLICE)  // 8 D-subtiles per CTA
#define TILE_E (TQ * LDSK)
#define NBLK16 (D_N / 16)            // 2048 16-col blocks per row
#define MARGIN 1.25f
#define CAND_CAP 256

// ---- device scratch ----
__device__ __half g_qh[Q_N * DIM];
__device__ __half g_dh[D_N * DIM];
__device__ unsigned short g_lmax16[(size_t)Q_N * NBLK16];   // 16 MB, f16 bits
__device__ float g_ms[Q_N];
__device__ float g_comb[Q_N];
__device__ int   g_done;

// ---- helpers ----
__device__ __forceinline__ uint32_t smem_u32(const void* p) {
    uint32_t a;
    asm("{ .reg .u64 t; cvta.to.shared.u64 t, %1; cvt.u32.u64 %0, t; }" : "=r"(a) : "l"(p));
    return a;
}
__device__ __forceinline__ void cpa16(void* s, const void* g) {
    unsigned sa = smem_u32(s);
    asm volatile("cp.async.cg.shared.global [%0], [%1], 16;" :: "r"(sa), "l"(g));
}
#define CP_COMMIT() asm volatile("cp.async.commit_group;" ::: "memory")
#define CP_WAIT0()  asm volatile("cp.async.wait_group 0;" ::: "memory")

__device__ __forceinline__ void load_tile(__half* dst, const __half* gsrc, int tid) {
#pragma unroll
    for (int t = 0; t < 8; t++) {
        int chunk = tid + t * 256;
        int row = chunk >> 4;
        int c   = chunk & 15;
        cpa16(dst + row * LDSK + c * 8, gsrc + row * DIM + c * 8);
    }
}
__device__ __forceinline__ void ldm_x4(uint32_t* r, uint32_t addr) {
    asm volatile("ldmatrix.sync.aligned.m8n8.x4.shared.b16 {%0,%1,%2,%3}, [%4];"
        : "=r"(r[0]), "=r"(r[1]), "=r"(r[2]), "=r"(r[3]) : "r"(addr));
}
// f16 x f16 -> f16 accum mma
__device__ __forceinline__ void mma_f16(uint32_t* c, const uint32_t* a, uint32_t b0, uint32_t b1) {
    asm volatile(
        "mma.sync.aligned.m16n8k16.row.col.f16.f16.f16.f16 "
        "{%0,%1}, {%2,%3,%4,%5}, {%6,%7}, {%0,%1};\n"
        : "+r"(c[0]), "+r"(c[1])
        : "r"(a[0]), "r"(a[1]), "r"(a[2]), "r"(a[3]), "r"(b0), "r"(b1));
}
__device__ __forceinline__ float bits_f16(unsigned short u) {
    __half h = *reinterpret_cast<__half*>(&u);
    return __half2float(h);
}
__device__ __forceinline__ uint32_t pack_h2(float a, float b) {
    __half2 h = __floats2half2_rn(a, b);
    return *reinterpret_cast<uint32_t*>(&h);
}

// =====================================================================
// Pass 0: fp32 -> fp16, 32B-read / 16B-write per step; reset counter
// =====================================================================
__global__ void convert_kernel(const float4* __restrict__ qe, const float4* __restrict__ de) {
    const int i = blockIdx.x * blockDim.x + threadIdx.x;   // 0 .. D_N*DIM/8-1
    {
        float4 v0 = de[2 * i], v1 = de[2 * i + 1];
        uint4 o;
        o.x = pack_h2(v0.x, v0.y); o.y = pack_h2(v0.z, v0.w);
        o.z = pack_h2(v1.x, v1.y); o.w = pack_h2(v1.z, v1.w);
        ((uint4*)g_dh)[i] = o;
    }
    if (i < Q_N * DIM / 8) {
        float4 v0 = qe[2 * i], v1 = qe[2 * i + 1];
        uint4 o;
        o.x = pack_h2(v0.x, v0.y); o.y = pack_h2(v0.z, v0.w);
        o.z = pack_h2(v1.x, v1.y); o.w = pack_h2(v1.z, v1.w);
        ((uint4*)g_qh)[i] = o;
    }
    if (i == 0) g_done = 0;
}

// =====================================================================
// Pass 1: f16 GEMM (f16 accum), A register-resident, B-only smem traffic,
//         per-(row, 16-col block) f16 max table  [identical to R12]
// =====================================================================
__global__ __launch_bounds__(256, 2) void approx_kernel() {
    extern __shared__ __half sm[];
    __half* As    = sm;                 // [128 x LDSK]
    __half* Bbase = As + TILE_E;        // 2 x [128 x LDSK]

    const int tid  = threadIdx.x;
    const int wid  = tid >> 5;
    const int lane = tid & 31;
    const int g    = lane >> 2;
    const int qr   = lane & 3;
    const int wid_m = wid >> 1;
    const int wid_n = wid & 1;
    const int qtile = blockIdx.x;
    const int d0    = blockIdx.y * (SUBS * TN);

    load_tile(As, g_qh + (size_t)qtile * TQ * DIM, tid);
    load_tile(Bbase, g_dh + (size_t)d0 * DIM, tid);
    CP_COMMIT();

    const int rowA  = wid_m * 32 + (lane & 15);
    const int colAb = ((lane >> 4) & 1) * 16;
    const uint32_t aBase = smem_u32(As) + rowA * ROWB + colAb;
    const int rowB  = wid_n * 64 + (lane & 7) + ((lane >> 4) << 3);
    const int colBb = ((lane >> 3) & 1) * 16;
    const uint32_t b_lane_off = (uint32_t)(rowB * ROWB + colBb);
    const uint32_t b_smem0 = smem_u32(Bbase);

    const int row0 = qtile * TQ + wid_m * 32 + g;

    CP_WAIT0();
    __syncthreads();

    uint32_t aF[2][8][4];
#pragma unroll
    for (int ks = 0; ks < 8; ks++) {
        ldm_x4(aF[0][ks], aBase + (uint32_t)(ks * 32));
        ldm_x4(aF[1][ks], aBase + 16 * ROWB + (uint32_t)(ks * 32));
    }

    for (int s = 0; s < SUBS; s++) {
        if (s > 0) { CP_WAIT0(); __syncthreads(); }
        if (s + 1 < SUBS) {
            load_tile(Bbase + ((s + 1) & 1) * TILE_E, g_dh + (size_t)(d0 + (s + 1) * TN) * DIM, tid);
            CP_COMMIT();
        }
        const uint32_t bH_base = b_smem0 + (uint32_t)(s & 1) * (TILE_E * 2) + b_lane_off;

        uint32_t acc[2][8][2];
#pragma unroll
        for (int mt = 0; mt < 2; mt++)
#pragma unroll
            for (int nt = 0; nt < 8; nt++) { acc[mt][nt][0] = 0u; acc[mt][nt][1] = 0u; }

#pragma unroll
        for (int ks = 0; ks < 8; ks++) {
            const uint32_t ko = (uint32_t)(ks * 32);
            uint32_t bH[4][4];
#pragma unroll
            for (int p = 0; p < 4; p++)
                ldm_x4(bH[p], bH_base + (uint32_t)(p * 16 * ROWB) + ko);
#pragma unroll
            for (int mt = 0; mt < 2; mt++)
#pragma unroll
                for (int p = 0; p < 4; p++) {
                    mma_f16(acc[mt][2 * p],     aF[mt][ks], bH[p][0], bH[p][1]);
                    mma_f16(acc[mt][2 * p + 1], aF[mt][ks], bH[p][2], bH[p][3]);
                }
        }

        const int gblk = (blockIdx.y * SUBS + s) * 8 + wid_n * 4;
#pragma unroll
        for (int sl = 0; sl < 4; sl++) {
            const int mt = sl >> 1, rg = sl & 1;
            unsigned short outv[4];
#pragma unroll
            for (int b = 0; b < 4; b++) {
                __half2 h0 = *reinterpret_cast<const __half2*>(&acc[mt][2 * b][rg]);
                __half2 h1 = *reinterpret_cast<const __half2*>(&acc[mt][2 * b + 1][rg]);
                __half2 hm = __hmax2(h0, h1);
                float m = fmaxf(__half2float(__low2half(hm)), __half2float(__high2half(hm)));
#pragma unroll
                for (int off = 1; off < 4; off <<= 1)
                    m = fmaxf(m, __shfl_xor_sync(0xffffffffu, m, off));
                __half hv = __float2half_rn(m);
                outv[b] = *reinterpret_cast<unsigned short*>(&hv);
            }
            if (qr == 0) {
                ushort4 v; v.x = outv[0]; v.y = outv[1]; v.z = outv[2]; v.w = outv[3];
                *(ushort4*)(g_lmax16 + (size_t)(row0 + sl * 8) * NBLK16 + gblk) = v;
            }
        }
    }
}

// =====================================================================
// Pass 2: FUSED scan + exact + weight gather + (last block) final reduce
// =====================================================================
__global__ void __launch_bounds__(256) scanexact_kernel(const float* __restrict__ qe,
                                                        const float* __restrict__ de,
                                                        const int* __restrict__ qids,
                                                        const int* __restrict__ dids,
                                                        const float* __restrict__ qwt,
                                                        const float* __restrict__ dwt,
                                                        float* __restrict__ out) {
    const int row = blockIdx.x;
    const int t   = threadIdx.x;
    const int wid  = t >> 5;
    const int lane = t & 31;
    const bool hi  = (lane >= 16);
    __shared__ float red[256];
    __shared__ float sC[256];
    __shared__ int lcnt;
    __shared__ int sdone;
    __shared__ uint32_t lblk[CAND_CAP];
    __shared__ float    cval[CAND_CAP];
    __shared__ unsigned ccol[CAND_CAP];

    // --- scan phase ---
    uint4 raw = ((const uint4*)(g_lmax16 + (size_t)row * NBLK16))[t];
    float v[8];
    v[0] = bits_f16((unsigned short)(raw.x & 0xFFFF));
    v[1] = bits_f16((unsigned short)(raw.x >> 16));
    v[2] = bits_f16((unsigned short)(raw.y & 0xFFFF));
    v[3] = bits_f16((unsigned short)(raw.y >> 16));
    v[4] = bits_f16((unsigned short)(raw.z & 0xFFFF));
    v[5] = bits_f16((unsigned short)(raw.z >> 16));
    v[6] = bits_f16((unsigned short)(raw.w & 0xFFFF));
    v[7] = bits_f16((unsigned short)(raw.w >> 16));

    float m = v[0];
#pragma unroll
    for (int j = 1; j < 8; j++) m = fmaxf(m, v[j]);
    red[t] = m;
    if (t == 0) lcnt = 0;
    __syncthreads();
    for (int off = 128; off > 0; off >>= 1) {
        if (t < off) red[t] = fmaxf(red[t], red[t + off]);
        __syncthreads();
    }
    const float thr = red[0] - MARGIN;

#pragma unroll
    for (int j = 0; j < 8; j++) {
        if (v[j] >= thr) {
            int p = atomicAdd(&lcnt, 1);
            if (p < CAND_CAP) lblk[p] = (uint32_t)(t * 8 + j);
        }
    }
    __syncthreads();
    const int cnt = lcnt < CAND_CAP ? lcnt : CAND_CAP;

    // --- exact phase: warp e-strided over candidates ---
    const float4 q4 = ((const float4*)(qe + (size_t)row * DIM))[lane];

    for (int e = wid; e < cnt; e += 8) {
        const int col0 = (int)lblk[e] * 16;

        float p[16];
#pragma unroll
        for (int b = 0; b < 2; b++) {
            float4 d[8];
#pragma unroll
            for (int r = 0; r < 8; r++)
                d[r] = ((const float4*)(de + (size_t)(col0 + b * 8 + r) * DIM))[lane];
#pragma unroll
            for (int r = 0; r < 8; r++)
                p[b * 8 + r] = fmaf(q4.x, d[r].x, fmaf(q4.y, d[r].y, fmaf(q4.z, d[r].z, q4.w * d[r].w)));
        }

        float y[8];
#pragma unroll
        for (int j = 0; j < 8; j++) {
            float a = hi ? p[j + 8] : p[j];
            float b = hi ? p[j] : p[j + 8];
            y[j] = a + __shfl_xor_sync(0xffffffffu, b, 16);
        }
#pragma unroll
        for (int off = 1; off < 16; off <<= 1)
#pragma unroll
            for (int j = 0; j < 8; j++)
                y[j] += __shfl_xor_sync(0xffffffffu, y[j], off);

        float    s = y[0];
        unsigned c = (unsigned)(col0 + (hi ? 8 : 0));
#pragma unroll
        for (int j = 1; j < 8; j++)
            if (y[j] > s) { s = y[j]; c = (unsigned)(col0 + (hi ? 8 : 0) + j); }
        {
            float    os = __shfl_xor_sync(0xffffffffu, s, 16);
            unsigned oc = __shfl_xor_sync(0xffffffffu, c, 16);
            if (os > s || (os == s && oc < c)) { s = os; c = oc; }
        }
        if (lane == 0) { cval[e] = s; ccol[e] = c; }
    }
    __syncthreads();

    // --- final per-row reduce (warp 0); ties -> smaller column ---
    if (t < 32) {
        float    s = -3.402823466e38f;
        unsigned c = 0xFFFFFFFFu;
        for (int e = lane; e < cnt; e += 32) {
            float    es = cval[e];
            unsigned ec = ccol[e];
            if (es > s || (es == s && ec < c)) { s = es; c = ec; }
        }
#pragma unroll
        for (int off = 1; off < 32; off <<= 1) {
            float    os = __shfl_xor_sync(0xffffffffu, s, off);
            unsigned oc = __shfl_xor_sync(0xffffffffu, c, off);
            if (os > s || (os == s && oc < c)) { s = os; c = oc; }
        }
        if (lane == 0) {
            g_ms[row]   = s;
            g_comb[row] = qwt[qids[row]] * dwt[dids[(int)c]];
        }
    }

    // --- last block to finish performs the global reduction (fixed order
    //     -> deterministic result regardless of which block runs it) ---
    if (t == 0) {
        __threadfence();
        int prev = atomicAdd(&g_done, 1);
        sdone = (prev == Q_N - 1) ? 1 : 0;
    }
    __syncthreads();
    if (sdone) {
        __threadfence();                        // acquire all rows' g_ms/g_comb
        float a = 0.f, b = 0.f, c = 0.f;
#pragma unroll
        for (int j = 0; j < Q_N / 1024; j++) {  // 4 float4 strides
            float4 cm = ((const float4*)g_comb)[t + j * 256];
            float4 ms = ((const float4*)g_ms)[t + j * 256];
            a += (cm.x + cm.y) + (cm.z + cm.w);
            b += fmaf(cm.x, ms.x, fmaf(cm.y, ms.y, fmaf(cm.z, ms.z, cm.w * ms.w)));
            c += (ms.x + ms.y) + (ms.z + ms.w);
        }
        red[t] = a; cval[t] = b; sC[t] = c;
        __syncthreads();
        for (int off = 128; off > 0; off >>= 1) {
            if (t < off) { red[t] += red[t + off]; cval[t] += cval[t + off]; sC[t] += sC[t + off]; }
            __syncthreads();
        }
        if (t == 0) out[0] = (red[0] > 0.f) ? (cval[0] / red[0]) : (sC[0] / (float)Q_N);
    }
}

// =====================================================================
// launch
// =====================================================================
extern "C" void kernel_launch(void* const* d_in, const int* in_sizes, int n_in,
                              void* d_out, int out_size) {
    const float* qe  = (const float*)d_in[0];
    const float* de  = (const float*)d_in[1];
    const int*   qid = (const int*)d_in[2];
    const int*   did = (const int*)d_in[3];
    const float* qwt = (const float*)d_in[4];
    const float* dwt = (const float*)d_in[5];
    float* out = (float*)d_out;

    size_t smem = (size_t)(3 * TILE_E) * sizeof(__half);   // 104,448 B -> 2 CTAs/SM
    cudaFuncSetAttribute(approx_kernel, cudaFuncAttributeMaxDynamicSharedMemorySize, (int)smem);

    convert_kernel<<<D_N * DIM / 8 / 256, 256>>>((const float4*)qe, (const float4*)de);
    approx_kernel<<<dim3(Q_N / TQ, NSLICE), 256, smem>>>();
    scanexact_kernel<<<Q_N, 256>>>(qe, de, qid, did, qwt, dwt, out);
}

// round 15
// speedup vs baseline: 1.0765x; 1.0679x over previous
#include <cuda_runtime.h>
#include <cuda_fp16.h>
#include <stdint.h>

#define Q_N   4096
#define D_N   32768
#define DIM   128
#define TQ    128
#define TN    128
#define LDSK  136                    // padded smem row stride in f16 elems (272 B)
#define ROWB  272
#define NSLICE 32
#define SUBS  ((D_N / TN) / NSLICE)  // 8 D-subtiles per CTA
#define TILE_E (TQ * LDSK)
#define NBLK16 (D_N / 16)            // 2048 16-col blocks per row
#define MARGIN 1.25f
#define CAND_CAP 256

// ---- device scratch ----
__device__ __half g_qh[Q_N * DIM];
__device__ __half g_dh[D_N * DIM];
__device__ unsigned short g_lmax16[(size_t)Q_N * NBLK16];   // 16 MB, f16 bits
__device__ float g_ms[Q_N];
__device__ float g_comb[Q_N];

// ---- helpers ----
__device__ __forceinline__ uint32_t smem_u32(const void* p) {
    uint32_t a;
    asm("{ .reg .u64 t; cvta.to.shared.u64 t, %1; cvt.u32.u64 %0, t; }" : "=r"(a) : "l"(p));
    return a;
}
__device__ __forceinline__ void cpa16(void* s, const void* g) {
    unsigned sa = smem_u32(s);
    asm volatile("cp.async.cg.shared.global [%0], [%1], 16;" :: "r"(sa), "l"(g));
}
#define CP_COMMIT() asm volatile("cp.async.commit_group;" ::: "memory")
#define CP_WAIT0()  asm volatile("cp.async.wait_group 0;" ::: "memory")

__device__ __forceinline__ void load_tile(__half* dst, const __half* gsrc, int tid) {
#pragma unroll
    for (int t = 0; t < 8; t++) {
        int chunk = tid + t * 256;
        int row = chunk >> 4;
        int c   = chunk & 15;
        cpa16(dst + row * LDSK + c * 8, gsrc + row * DIM + c * 8);
    }
}
__device__ __forceinline__ void ldm_x4(uint32_t* r, uint32_t addr) {
    asm volatile("ldmatrix.sync.aligned.m8n8.x4.shared.b16 {%0,%1,%2,%3}, [%4];"
        : "=r"(r[0]), "=r"(r[1]), "=r"(r[2]), "=r"(r[3]) : "r"(addr));
}
// f16 x f16 -> f16 accum mma
__device__ __forceinline__ void mma_f16(uint32_t* c, const uint32_t* a, uint32_t b0, uint32_t b1) {
    asm volatile(
        "mma.sync.aligned.m16n8k16.row.col.f16.f16.f16.f16 "
        "{%0,%1}, {%2,%3,%4,%5}, {%6,%7}, {%0,%1};\n"
        : "+r"(c[0]), "+r"(c[1])
        : "r"(a[0]), "r"(a[1]), "r"(a[2]), "r"(a[3]), "r"(b0), "r"(b1));
}
__device__ __forceinline__ float bits_f16(unsigned short u) {
    __half h = *reinterpret_cast<__half*>(&u);
    return __half2float(h);
}
__device__ __forceinline__ uint32_t pack_h2(float a, float b) {
    __half2 h = __floats2half2_rn(a, b);
    return *reinterpret_cast<uint32_t*>(&h);
}

// =====================================================================
// Pass 0: fp32 -> fp16, 32B-read / 16B-write per step
// =====================================================================
__global__ void convert_kernel(const float4* __restrict__ qe, const float4* __restrict__ de) {
    const int i = blockIdx.x * blockDim.x + threadIdx.x;   // 0 .. D_N*DIM/8-1
    {
        float4 v0 = de[2 * i], v1 = de[2 * i + 1];
        uint4 o;
        o.x = pack_h2(v0.x, v0.y); o.y = pack_h2(v0.z, v0.w);
        o.z = pack_h2(v1.x, v1.y); o.w = pack_h2(v1.z, v1.w);
        ((uint4*)g_dh)[i] = o;
    }
    if (i < Q_N * DIM / 8) {
        float4 v0 = qe[2 * i], v1 = qe[2 * i + 1];
        uint4 o;
        o.x = pack_h2(v0.x, v0.y); o.y = pack_h2(v0.z, v0.w);
        o.z = pack_h2(v1.x, v1.y); o.w = pack_h2(v1.z, v1.w);
        ((uint4*)g_qh)[i] = o;
    }
}

// =====================================================================
// Pass 1: f16 GEMM (f16 accum), A register-resident, B-only smem traffic,
//         per-(row, 16-col block) f16 max table  [identical to R12]
// =====================================================================
__global__ __launch_bounds__(256, 2) void approx_kernel() {
    extern __shared__ __half sm[];
    __half* As    = sm;                 // [128 x LDSK]
    __half* Bbase = As + TILE_E;        // 2 x [128 x LDSK]

    const int tid  = threadIdx.x;
    const int wid  = tid >> 5;
    const int lane = tid & 31;
    const int g    = lane >> 2;
    const int qr   = lane & 3;
    const int wid_m = wid >> 1;
    const int wid_n = wid & 1;
    const int qtile = blockIdx.x;
    const int d0    = blockIdx.y * (SUBS * TN);

    load_tile(As, g_qh + (size_t)qtile * TQ * DIM, tid);
    load_tile(Bbase, g_dh + (size_t)d0 * DIM, tid);
    CP_COMMIT();

    const int rowA  = wid_m * 32 + (lane & 15);
    const int colAb = ((lane >> 4) & 1) * 16;
    const uint32_t aBase = smem_u32(As) + rowA * ROWB + colAb;
    const int rowB  = wid_n * 64 + (lane & 7) + ((lane >> 4) << 3);
    const int colBb = ((lane >> 3) & 1) * 16;
    const uint32_t b_lane_off = (uint32_t)(rowB * ROWB + colBb);
    const uint32_t b_smem0 = smem_u32(Bbase);

    const int row0 = qtile * TQ + wid_m * 32 + g;

    CP_WAIT0();
    __syncthreads();

    uint32_t aF[2][8][4];
#pragma unroll
    for (int ks = 0; ks < 8; ks++) {
        ldm_x4(aF[0][ks], aBase + (uint32_t)(ks * 32));
        ldm_x4(aF[1][ks], aBase + 16 * ROWB + (uint32_t)(ks * 32));
    }

    for (int s = 0; s < SUBS; s++) {
        if (s > 0) { CP_WAIT0(); __syncthreads(); }
        if (s + 1 < SUBS) {
            load_tile(Bbase + ((s + 1) & 1) * TILE_E, g_dh + (size_t)(d0 + (s + 1) * TN) * DIM, tid);
            CP_COMMIT();
        }
        const uint32_t bH_base = b_smem0 + (uint32_t)(s & 1) * (TILE_E * 2) + b_lane_off;

        uint32_t acc[2][8][2];
#pragma unroll
        for (int mt = 0; mt < 2; mt++)
#pragma unroll
            for (int nt = 0; nt < 8; nt++) { acc[mt][nt][0] = 0u; acc[mt][nt][1] = 0u; }

#pragma unroll
        for (int ks = 0; ks < 8; ks++) {
            const uint32_t ko = (uint32_t)(ks * 32);
            uint32_t bH[4][4];
#pragma unroll
            for (int p = 0; p < 4; p++)
                ldm_x4(bH[p], bH_base + (uint32_t)(p * 16 * ROWB) + ko);
#pragma unroll
            for (int mt = 0; mt < 2; mt++)
#pragma unroll
                for (int p = 0; p < 4; p++) {
                    mma_f16(acc[mt][2 * p],     aF[mt][ks], bH[p][0], bH[p][1]);
                    mma_f16(acc[mt][2 * p + 1], aF[mt][ks], bH[p][2], bH[p][3]);
                }
        }

        const int gblk = (blockIdx.y * SUBS + s) * 8 + wid_n * 4;
#pragma unroll
        for (int sl = 0; sl < 4; sl++) {
            const int mt = sl >> 1, rg = sl & 1;
            unsigned short outv[4];
#pragma unroll
            for (int b = 0; b < 4; b++) {
                __half2 h0 = *reinterpret_cast<const __half2*>(&acc[mt][2 * b][rg]);
                __half2 h1 = *reinterpret_cast<const __half2*>(&acc[mt][2 * b + 1][rg]);
                __half2 hm = __hmax2(h0, h1);
                float m = fmaxf(__half2float(__low2half(hm)), __half2float(__high2half(hm)));
#pragma unroll
                for (int off = 1; off < 4; off <<= 1)
                    m = fmaxf(m, __shfl_xor_sync(0xffffffffu, m, off));
                __half hv = __float2half_rn(m);
                outv[b] = *reinterpret_cast<unsigned short*>(&hv);
            }
            if (qr == 0) {
                ushort4 v; v.x = outv[0]; v.y = outv[1]; v.z = outv[2]; v.w = outv[3];
                *(ushort4*)(g_lmax16 + (size_t)(row0 + sl * 8) * NBLK16 + gblk) = v;
            }
        }
    }
}

// =====================================================================
// Pass 2: FUSED scan + exact + weight gather (no fences, no counter)
// =====================================================================
__global__ void __launch_bounds__(256) scanexact_kernel(const float* __restrict__ qe,
                                                        const float* __restrict__ de,
                                                        const int* __restrict__ qids,
                                                        const int* __restrict__ dids,
                                                        const float* __restrict__ qwt,
                                                        const float* __restrict__ dwt) {
    const int row = blockIdx.x;
    const int t   = threadIdx.x;
    const int wid  = t >> 5;
    const int lane = t & 31;
    const bool hi  = (lane >= 16);
    __shared__ float red[256];
    __shared__ int lcnt;
    __shared__ uint32_t lblk[CAND_CAP];
    __shared__ float    cval[CAND_CAP];
    __shared__ unsigned ccol[CAND_CAP];

    // --- scan phase ---
    uint4 raw = ((const uint4*)(g_lmax16 + (size_t)row * NBLK16))[t];
    float v[8];
    v[0] = bits_f16((unsigned short)(raw.x & 0xFFFF));
    v[1] = bits_f16((unsigned short)(raw.x >> 16));
    v[2] = bits_f16((unsigned short)(raw.y & 0xFFFF));
    v[3] = bits_f16((unsigned short)(raw.y >> 16));
    v[4] = bits_f16((unsigned short)(raw.z & 0xFFFF));
    v[5] = bits_f16((unsigned short)(raw.z >> 16));
    v[6] = bits_f16((unsigned short)(raw.w & 0xFFFF));
    v[7] = bits_f16((unsigned short)(raw.w >> 16));

    float m = v[0];
#pragma unroll
    for (int j = 1; j < 8; j++) m = fmaxf(m, v[j]);
    red[t] = m;
    if (t == 0) lcnt = 0;
    __syncthreads();
    for (int off = 128; off > 0; off >>= 1) {
        if (t < off) red[t] = fmaxf(red[t], red[t + off]);
        __syncthreads();
    }
    const float thr = red[0] - MARGIN;

#pragma unroll
    for (int j = 0; j < 8; j++) {
        if (v[j] >= thr) {
            int p = atomicAdd(&lcnt, 1);
            if (p < CAND_CAP) lblk[p] = (uint32_t)(t * 8 + j);
        }
    }
    __syncthreads();
    const int cnt = lcnt < CAND_CAP ? lcnt : CAND_CAP;

    // --- exact phase: warp e-strided over candidates ---
    const float4 q4 = ((const float4*)(qe + (size_t)row * DIM))[lane];

    for (int e = wid; e < cnt; e += 8) {
        const int col0 = (int)lblk[e] * 16;

        float p[16];
#pragma unroll
        for (int b = 0; b < 2; b++) {
            float4 d[8];
#pragma unroll
            for (int r = 0; r < 8; r++)
                d[r] = ((const float4*)(de + (size_t)(col0 + b * 8 + r) * DIM))[lane];
#pragma unroll
            for (int r = 0; r < 8; r++)
                p[b * 8 + r] = fmaf(q4.x, d[r].x, fmaf(q4.y, d[r].y, fmaf(q4.z, d[r].z, q4.w * d[r].w)));
        }

        float y[8];
#pragma unroll
        for (int j = 0; j < 8; j++) {
            float a = hi ? p[j + 8] : p[j];
            float b = hi ? p[j] : p[j + 8];
            y[j] = a + __shfl_xor_sync(0xffffffffu, b, 16);
        }
#pragma unroll
        for (int off = 1; off < 16; off <<= 1)
#pragma unroll
            for (int j = 0; j < 8; j++)
                y[j] += __shfl_xor_sync(0xffffffffu, y[j], off);

        float    s = y[0];
        unsigned c = (unsigned)(col0 + (hi ? 8 : 0));
#pragma unroll
        for (int j = 1; j < 8; j++)
            if (y[j] > s) { s = y[j]; c = (unsigned)(col0 + (hi ? 8 : 0) + j); }
        {
            float    os = __shfl_xor_sync(0xffffffffu, s, 16);
            unsigned oc = __shfl_xor_sync(0xffffffffu, c, 16);
            if (os > s || (os == s && oc < c)) { s = os; c = oc; }
        }
        if (lane == 0) { cval[e] = s; ccol[e] = c; }
    }
    __syncthreads();

    // --- final per-row reduce (warp 0); ties -> smaller column ---
    if (t < 32) {
        float    s = -3.402823466e38f;
        unsigned c = 0xFFFFFFFFu;
        for (int e = lane; e < cnt; e += 32) {
            float    es = cval[e];
            unsigned ec = ccol[e];
            if (es > s || (es == s && ec < c)) { s = es; c = ec; }
        }
#pragma unroll
        for (int off = 1; off < 32; off <<= 1) {
            float    os = __shfl_xor_sync(0xffffffffu, s, off);
            unsigned oc = __shfl_xor_sync(0xffffffffu, c, off);
            if (os > s || (os == s && oc < c)) { s = os; c = oc; }
        }
        if (lane == 0) {
            g_ms[row]   = s;
            g_comb[row] = qwt[qids[row]] * dwt[dids[(int)c]];
        }
    }
}

// =====================================================================
// Pass 3: coalesced reduction over g_ms/g_comb -> final scalar
// =====================================================================
__global__ void finalize_kernel(float* __restrict__ out) {
    __shared__ float sA[256], sB[256], sC[256];
    int tid = threadIdx.x;
    float a = 0.f, b = 0.f, c = 0.f;
#pragma unroll
    for (int j = 0; j < Q_N / 1024; j++) {               // 4 float4 strides
        float4 cm = ((const float4*)g_comb)[tid + j * 256];
        float4 ms = ((const float4*)g_ms)[tid + j * 256];
        a += (cm.x + cm.y) + (cm.z + cm.w);
        b += fmaf(cm.x, ms.x, fmaf(cm.y, ms.y, fmaf(cm.z, ms.z, cm.w * ms.w)));
        c += (ms.x + ms.y) + (ms.z + ms.w);
    }
    sA[tid] = a; sB[tid] = b; sC[tid] = c;
    __syncthreads();
    for (int off = 128; off > 0; off >>= 1) {
        if (tid < off) { sA[tid] += sA[tid + off]; sB[tid] += sB[tid + off]; sC[tid] += sC[tid + off]; }
        __syncthreads();
    }
    if (tid == 0) out[0] = (sA[0] > 0.f) ? (sB[0] / sA[0]) : (sC[0] / (float)Q_N);
}

// =====================================================================
// launch
// =====================================================================
extern "C" void kernel_launch(void* const* d_in, const int* in_sizes, int n_in,
                              void* d_out, int out_size) {
    const float* qe  = (const float*)d_in[0];
    const float* de  = (const float*)d_in[1];
    const int*   qid = (const int*)d_in[2];
    const int*   did = (const int*)d_in[3];
    const float* qwt = (const float*)d_in[4];
    const float* dwt = (const float*)d_in[5];
    float* out = (float*)d_out;

    size_t smem = (size_t)(3 * TILE_E) * sizeof(__half);   // 104,448 B -> 2 CTAs/SM
    cudaFuncSetAttribute(approx_kernel, cudaFuncAttributeMaxDynamicSharedMemorySize, (int)smem);

    convert_kernel<<<D_N * DIM / 8 / 256, 256>>>((const float4*)qe, (const float4*)de);
    approx_kernel<<<dim3(Q_N / TQ, NSLICE), 256, smem>>>();
    scanexact_kernel<<<Q_N, 256>>>(qe, de, qid, did, qwt, dwt);
    finalize_kernel<<<1, 256>>>(out);
}